// round 7
// baseline (speedup 1.0000x reference)
#include <cuda_runtime.h>
#include <cuda_bf16.h>
#include <math.h>

#define BB 8
#define PP 2048
#define CC 21
#define CENTER_VAR 0.1f
#define SIZE_VAR 0.2f
#define GEPS 1e-8f

#define NBLK 64
#define NTHR 256
#define NWARP (NTHR / 32)

// Scratch (device globals; zeroed at load; reset by finalizer each run)
__device__ float4   g_boxA[BB][PP];
__device__ float4   g_boxT[BB][PP];
__device__ int      g_cntA[BB];
__device__ int      g_cntT[BB];
__device__ unsigned g_fin;   // monotonic ticket: last arriver runs the tail

__device__ __forceinline__ float4 decode_box(float4 l, float4 pr) {
    float cx = pr.x + l.x * CENTER_VAR * pr.z;
    float cy = pr.y + l.y * CENTER_VAR * pr.w;
    float w  = pr.z * __expf(l.z * SIZE_VAR);
    float h  = pr.w * __expf(l.w * SIZE_VAR);
    float x0 = cx - 0.5f * w;
    float y0 = cy - 0.5f * h;
    return make_float4(x0, y0, x0 + w, y0 + h);
}

__global__ void __launch_bounds__(NTHR, 1)
iou_loss_fused(const float* __restrict__ conf,
               const float* __restrict__ loc,
               const int*   __restrict__ tc,
               const float* __restrict__ tloc,
               const float* __restrict__ priors,
               float* __restrict__ out) {
    const int tid  = threadIdx.x;
    const int bid  = blockIdx.x;
    const int lane = tid & 31;
    const int wid  = tid >> 5;
    const int idx  = bid * NTHR + tid;     // exactly BB*PP threads
    const int b    = idx >> 11;
    const int p    = idx & (PP - 1);

    // ---- Warp-coalesced conf staging into smem ------------------------------
    __shared__ float s_conf[NWARP][32 * CC];
    {
        const float4* g4 = (const float4*)(conf + (size_t)(bid * NTHR + wid * 32) * CC);
        float4* s4 = (float4*)s_conf[wid];
        #pragma unroll
        for (int i = 0; i < 6; i++) {
            int j = i * 32 + lane;
            if (j < (32 * CC) / 4) s4[j] = g4[j];
        }
    }

    float4 pr = ((const float4*)priors)[p];
    float4 lt = ((const float4*)tloc)[idx];
    float4 ll = ((const float4*)loc)[idx];

    // ---- dtype probe (block-local). int64 LE {0,1} -> odd words all zero ---
    int w0 = (tid < 128) ? tc[2 * tid + 1] : 0;
    const bool is64 = (__syncthreads_or(w0) == 0);   // also orders smem staging
    const int tv = is64 ? tc[2 * idx] : tc[idx];

    // ---- Unconditional compute ----------------------------------------------
    float4 boxT = decode_box(lt, pr);
    float4 boxA = decode_box(ll, pr);

    const float* cf = &s_conf[wid][lane * CC];
    float m = cf[0]; int mi = 0;
    #pragma unroll
    for (int c = 1; c < CC; c++) {
        float v = cf[c];
        if (v > m) { m = v; mi = c; }
    }
    float se = 0.f;
    #pragma unroll
    for (int c = 0; c < CC; c++) se += __expf(cf[c] - m);
    if (fabsf(se - 2.0f) < 1e-3f) {   // threshold guard: redo in full precision
        se = 0.f;
        #pragma unroll
        for (int c = 0; c < CC; c++) se += expf(cf[c] - m);
    }

    const bool isT = (tv > 0);
    const bool isA = isT && (se < 2.0f) && (mi > 0);   // maxp = 1/se > 0.5

    // ---- Warp-aggregated compaction -----------------------------------------
    unsigned mT = __ballot_sync(0xffffffffu, isT);
    if (mT) {
        int ldr = __ffs(mT) - 1, base;
        if (lane == ldr) base = atomicAdd(&g_cntT[b], __popc(mT));
        base = __shfl_sync(0xffffffffu, base, ldr);
        if (isT) g_boxT[b][base + __popc(mT & ((1u << lane) - 1u))] = boxT;
    }
    unsigned mA = __ballot_sync(0xffffffffu, isA);
    if (mA) {
        int ldr = __ffs(mA) - 1, base;
        if (lane == ldr) base = atomicAdd(&g_cntA[b], __popc(mA));
        base = __shfl_sync(0xffffffffu, base, ldr);
        if (isA) g_boxA[b][base + __popc(mA & ((1u << lane) - 1u))] = boxA;
    }

    // ---- Ticket: everyone but the last-arriving block EXITS (no spinning) ---
    __syncthreads();
    __shared__ int s_last;
    if (tid == 0) {
        __threadfence();                               // release this block's writes
        unsigned tk = atomicAdd(&g_fin, 1u);
        s_last = ((tk & (NBLK - 1u)) == (NBLK - 1u)) ? 1 : 0;
        if (s_last) __threadfence();                   // acquire all blocks' writes
    }
    __syncthreads();
    if (!s_last) return;

    // =========================================================================
    // TAIL (single block): phase 2 + finalize + scratch reset
    // =========================================================================
    __shared__ int   s_cT[BB];
    __shared__ int   s_nA[BB];
    __shared__ int   s_off[BB + 1];
    __shared__ float s_S[BB];
    if (tid < BB) {
        s_cT[tid] = g_cntT[tid];
        s_nA[tid] = g_cntA[tid];
        s_S[tid]  = 0.f;
        g_cntT[tid] = 0;                // reset for next graph replay
        g_cntA[tid] = 0;
    }
    __syncthreads();
    if (tid == 0) {
        int o = 0;
        #pragma unroll
        for (int q = 0; q < BB; q++) { s_off[q] = o; o += s_nA[q] * s_cT[q]; }
        s_off[BB] = o;
    }
    __syncthreads();
    const int total = s_off[BB];

    for (int k = tid; k < total; k += NTHR) {
        int bb = 0;
        #pragma unroll
        for (int q = 1; q < BB; q++) bb += (k >= s_off[q]);
        int lk = k - s_off[bb];
        int nt = s_cT[bb];
        int a  = lk / nt;
        int t  = lk - a * nt;

        float4 A = g_boxA[bb][a];
        float4 T = g_boxT[bb][t];
        float ix = fminf(A.z, T.z) - fmaxf(A.x, T.x);
        float iy = fminf(A.w, T.w) - fmaxf(A.y, T.y);
        float inter = fmaxf(ix, 0.f) * fmaxf(iy, 0.f);
        float areaA = (A.z - A.x) * (A.w - A.y);
        float areaT = (T.z - T.x) * (T.w - T.y);
        float uni = areaA + areaT - inter;
        float iou = __fdividef(inter, fmaxf(uni, GEPS));
        float ex = fmaxf(A.z, T.z) - fminf(A.x, T.x);
        float ey = fmaxf(A.w, T.w) - fminf(A.y, T.y);
        float enc = ex * ey;
        float g = iou - __fdividef(enc - uni, fmaxf(enc, GEPS));
        atomicAdd(&s_S[bb], g);
    }
    __syncthreads();

    if (tid < 32) {
        float term = 0.f, ntv = 0.f;
        if (tid < BB) {
            float nt = (float)s_cT[tid];
            float na = (float)s_nA[tid];
            bool bt = nt > 0.f, ba = na > 0.f;
            if (bt && ba)      term = nt - s_S[tid] / fmaxf(nt, 1.f);
            else if (bt != ba) term = 1.f;
            else               term = 0.f;
            ntv = nt;
        }
        #pragma unroll
        for (int o = 4; o > 0; o >>= 1) {
            term += __shfl_down_sync(0xffffffffu, term, o);
            ntv  += __shfl_down_sync(0xffffffffu, ntv, o);
        }
        if (tid == 0) out[0] = term / fmaxf(ntv, 1.f);
    }
}

extern "C" void kernel_launch(void* const* d_in, const int* in_sizes, int n_in,
                              void* d_out, int out_size) {
    const float* conf   = (const float*)d_in[0];
    const float* loc    = (const float*)d_in[1];
    const int*   tc     = (const int*)d_in[2];
    const float* tloc   = (const float*)d_in[3];
    const float* priors = (const float*)d_in[4];
    float* out = (float*)d_out;

    iou_loss_fused<<<NBLK, NTHR>>>(conf, loc, tc, tloc, priors, out);
}